// round 6
// baseline (speedup 1.0000x reference)
#include <cuda_runtime.h>
#include <cuda_fp16.h>

#define NA 50000
#define MN 12
#define NR (NA*MN)          // 600000
#define NCRY 5000
#define ORIGF 200
#define AFL 64
#define EPS 1e-5f
#define MT 96               // msg row tile = 8 atoms
#define NBLK (NR/MT)        // 6250

// ---------------- scratch ----------------------------------------------------
__device__ float g_atom[NA*AFL];
__device__ float g_S[NA*128];
__device__ float g_T[NA*128];
__device__ float g_psum[NBLK*128];
__device__ float g_psq [NBLK*128];
__device__ float g_r2s[125*128];
__device__ float g_r2q[125*128];
__device__ float g_A2[128];
__device__ float g_B2[128];
__device__ float g_summed[NA*AFL];
__device__ float g_p1s[NBLK*64];
__device__ float g_p1q[NBLK*64];
__device__ float g_r1s[125*64];
__device__ float g_r1q[125*64];
__device__ float g_A1[64];
__device__ float g_B1[64];
__device__ int   g_idx[NR];
__device__ int   g_flag;

// ---------------- MUFU transcendentals --------------------------------------
__device__ __forceinline__ float mufu_ex2(float x){ float y; asm("ex2.approx.f32 %0,%1;" : "=f"(y) : "f"(x)); return y; }
__device__ __forceinline__ float mufu_lg2(float x){ float y; asm("lg2.approx.f32 %0,%1;" : "=f"(y) : "f"(x)); return y; }
__device__ __forceinline__ float mufu_rcp(float x){ float y; asm("rcp.approx.f32 %0,%1;" : "=f"(y) : "f"(x)); return y; }
__device__ __forceinline__ float fsig_(float x){
    return mufu_rcp(1.0f + mufu_ex2(-1.4426950408889634f * x));
}
__device__ __forceinline__ float fsoftplus_(float x){
    float u = mufu_ex2(-1.4426950408889634f * fabsf(x));   // exp(-|x|)
    return fmaxf(x, 0.0f) + 0.69314718055994531f * mufu_lg2(1.0f + u);
}

// ---------------- tf32 mma helpers ------------------------------------------
__device__ __forceinline__ unsigned tf32r(float x){
    unsigned u; asm("cvt.rna.tf32.f32 %0, %1;" : "=r"(u) : "f"(x)); return u;
}
__device__ __forceinline__ void mma8(float& c0, float& c1, float& c2, float& c3,
                                     unsigned a0, unsigned a1, unsigned a2, unsigned a3,
                                     unsigned b0, unsigned b1){
    asm volatile("mma.sync.aligned.m16n8k8.row.col.f32.tf32.tf32.f32 "
        "{%0,%1,%2,%3}, {%4,%5,%6,%7}, {%8,%9}, {%0,%1,%2,%3};"
        : "+f"(c0), "+f"(c1), "+f"(c2), "+f"(c3)
        : "r"(a0), "r"(a1), "r"(a2), "r"(a3), "r"(b0), "r"(b1));
}

// ---------------- index dtype detect + convert ------------------------------
__global__ void k_detect(const int* __restrict__ raw){
    __shared__ int s[256];
    int nz = 0;
    for (int i = threadIdx.x; i < 2048; i += 256) nz |= (raw[2*i+1] != 0);
    s[threadIdx.x] = nz;
    __syncthreads();
    for (int off = 128; off; off >>= 1){
        if (threadIdx.x < off) s[threadIdx.x] |= s[threadIdx.x + off];
        __syncthreads();
    }
    if (threadIdx.x == 0) g_flag = (s[0] == 0) ? 1 : 0;
}
__global__ void k_conv(const int* __restrict__ raw){
    int i = blockIdx.x * 256 + threadIdx.x;
    if (i < NR){
        int f = g_flag;
        g_idx[i] = raw[f ? (2*i) : i];
    }
}

// ---------------- embedding via tf32 mma: atom = orig@embW + b --------------
// grid 391, 256 threads, 128 rows/block, K=200 (25 k-steps), N=64
__global__ void __launch_bounds__(256) k_embed2(const float* __restrict__ orig,
                                                const float* __restrict__ W,
                                                const float* __restrict__ B){
    extern __shared__ float sm[];
    float* As  = sm;            // 128 x 204
    float* WTs = sm + 26112;    // 64 x 204
    float* Bs  = sm + 39168;    // 64
    int t = threadIdx.x;
    int lane = t & 31, warp = t >> 5;
    int gr = lane >> 2, q = lane & 3;
    int r0 = blockIdx.x * 128;

    for (int i = t; i < 128*ORIGF; i += 256){
        int r = i / ORIGF, k = i - r*ORIGF;
        int row = r0 + r;
        As[r*204 + k] = (row < NA) ? __uint_as_float(tf32r(orig[(size_t)row*ORIGF + k])) : 0.0f;
    }
    for (int i = t; i < 64*ORIGF; i += 256){
        int n = i / ORIGF, k = i - n*ORIGF;
        WTs[n*204 + k] = __uint_as_float(tf32r(W[k*64 + n]));
    }
    if (t < 64) Bs[t] = B[t];
    __syncthreads();

    float acc[8][4];
    #pragma unroll
    for (int j = 0; j < 8; j++){ acc[j][0]=0; acc[j][1]=0; acc[j][2]=0; acc[j][3]=0; }
    int rb = warp * 16;
    for (int ks = 0; ks < 25; ks++){
        int k0 = ks*8 + q;
        unsigned a0 = __float_as_uint(As[(rb+gr)*204 + k0]);
        unsigned a1 = __float_as_uint(As[(rb+gr+8)*204 + k0]);
        unsigned a2 = __float_as_uint(As[(rb+gr)*204 + k0 + 4]);
        unsigned a3 = __float_as_uint(As[(rb+gr+8)*204 + k0 + 4]);
        #pragma unroll
        for (int j = 0; j < 8; j++){
            unsigned b0 = __float_as_uint(WTs[(j*8+gr)*204 + k0]);
            unsigned b1 = __float_as_uint(WTs[(j*8+gr)*204 + k0 + 4]);
            mma8(acc[j][0], acc[j][1], acc[j][2], acc[j][3], a0, a1, a2, a3, b0, b1);
        }
    }
    #pragma unroll
    for (int j = 0; j < 8; j++){
        int colb = j*8 + 2*q;
        float b0v = Bs[colb], b1v = Bs[colb+1];
        int row = r0 + rb + gr;
        if (row < NA){
            float2 v; v.x = acc[j][0] + b0v; v.y = acc[j][1] + b1v;
            *(float2*)(g_atom + row*64 + colb) = v;
        }
        row += 8;
        if (row < NA){
            float2 v; v.x = acc[j][2] + b0v; v.y = acc[j][3] + b1v;
            *(float2*)(g_atom + row*64 + colb) = v;
        }
    }
}

// ---------------- S/T via tf32 mma: grid (391, 2) ---------------------------
__global__ void __launch_bounds__(256) k_st2(const float* __restrict__ Wl,
                                             const float* __restrict__ bl){
    extern __shared__ float sm[];
    float* As  = sm;            // 128 x 68
    float* WTs = sm + 8704;     // 128 x 68
    float* Bs  = sm + 17408;    // 128
    int t = threadIdx.x;
    int lane = t & 31, warp = t >> 5;
    int gr = lane >> 2, q = lane & 3;
    int r0 = blockIdx.x * 128;
    int half = blockIdx.y;      // 0 -> S (+bias), 1 -> T

    for (int i = t; i < 128*64; i += 256){
        int r = i >> 6, k = i & 63;
        int row = r0 + r;
        As[r*68 + k] = (row < NA) ? __uint_as_float(tf32r(g_atom[row*64 + k])) : 0.0f;
    }
    const float* wsrc = Wl + half*64*128;
    for (int i = t; i < 64*128; i += 256){
        int k = i >> 7, n = i & 127;
        WTs[n*68 + k] = __uint_as_float(tf32r(wsrc[i]));
    }
    if (t < 128) Bs[t] = half ? 0.0f : bl[t];
    __syncthreads();

    float acc[16][4];
    #pragma unroll
    for (int j = 0; j < 16; j++){ acc[j][0]=0; acc[j][1]=0; acc[j][2]=0; acc[j][3]=0; }
    int rb = warp * 16;
    for (int ks = 0; ks < 8; ks++){
        int k0 = ks*8 + q;
        unsigned a0 = __float_as_uint(As[(rb+gr)*68 + k0]);
        unsigned a1 = __float_as_uint(As[(rb+gr+8)*68 + k0]);
        unsigned a2 = __float_as_uint(As[(rb+gr)*68 + k0 + 4]);
        unsigned a3 = __float_as_uint(As[(rb+gr+8)*68 + k0 + 4]);
        #pragma unroll
        for (int j = 0; j < 16; j++){
            unsigned b0 = __float_as_uint(WTs[(j*8+gr)*68 + k0]);
            unsigned b1 = __float_as_uint(WTs[(j*8+gr)*68 + k0 + 4]);
            mma8(acc[j][0], acc[j][1], acc[j][2], acc[j][3], a0, a1, a2, a3, b0, b1);
        }
    }
    float* dst = half ? g_T : g_S;
    #pragma unroll
    for (int j = 0; j < 16; j++){
        int colb = j*8 + 2*q;
        float b0v = Bs[colb], b1v = Bs[colb+1];
        int row = r0 + rb + gr;
        if (row < NA){
            float2 v; v.x = acc[j][0] + b0v; v.y = acc[j][1] + b1v;
            *(float2*)(dst + row*128 + colb) = v;
        }
        row += 8;
        if (row < NA){
            float2 v; v.x = acc[j][2] + b0v; v.y = acc[j][3] + b1v;
            *(float2*)(dst + row*128 + colb) = v;
        }
    }
}

// ======================= msg pass A: stats only ==============================
// smem floats: NFs[0,6528) WTs[6528,15232) | Zs alias [0,12672)
//              Ssm[15232,16256) rIdx@16256 (96 ints) ps[16352,16736) pq[16736,17120)
__global__ void __launch_bounds__(192) k_msgA(const float* __restrict__ Wl,
                                              const float* __restrict__ nbr){
    extern __shared__ float sm[];
    float* NFs = sm;
    float* WTs = sm + 6528;
    float* Zs  = sm;
    float* Ssm = sm + 15232;
    int*   rIdx= (int*)(sm + 16256);
    float* ps  = sm + 16352;
    float* pq  = sm + 16736;

    int t = threadIdx.x;
    int lane = t & 31, warp = t >> 5;
    int gr = lane >> 2, q = lane & 3;
    int blk = blockIdx.x;
    int r0 = blk * MT;

    const float* nsrc = nbr + (size_t)r0 * 64;
    for (int i = t; i < MT*64; i += 192){
        NFs[(i >> 6)*68 + (i & 63)] = __uint_as_float(tf32r(nsrc[i]));
    }
    const float* wsrc = Wl + 128*128;
    for (int i = t; i < 64*128; i += 192){
        int k = i >> 7, n = i & 127;
        WTs[n*68 + k] = __uint_as_float(tf32r(wsrc[i]));
    }
    for (int i = t; i < 1024; i += 192) Ssm[i] = g_S[(size_t)blk*8*128 + i];
    for (int i = t; i < MT;   i += 192) rIdx[i] = g_idx[r0 + i];
    __syncthreads();

    float acc[16][4];
    #pragma unroll
    for (int j = 0; j < 16; j++){ acc[j][0]=0; acc[j][1]=0; acc[j][2]=0; acc[j][3]=0; }
    int rb = warp * 16;
    for (int ks = 0; ks < 8; ks++){
        int k0 = ks*8 + q;
        unsigned a0 = __float_as_uint(NFs[(rb+gr)*68 + k0]);
        unsigned a1 = __float_as_uint(NFs[(rb+gr+8)*68 + k0]);
        unsigned a2 = __float_as_uint(NFs[(rb+gr)*68 + k0 + 4]);
        unsigned a3 = __float_as_uint(NFs[(rb+gr+8)*68 + k0 + 4]);
        #pragma unroll
        for (int j = 0; j < 16; j++){
            unsigned b0 = __float_as_uint(WTs[(j*8+gr)*68 + k0]);
            unsigned b1 = __float_as_uint(WTs[(j*8+gr)*68 + k0 + 4]);
            mma8(acc[j][0], acc[j][1], acc[j][2], acc[j][3], a0, a1, a2, a3, b0, b1);
        }
    }
    __syncthreads();
    #pragma unroll
    for (int j = 0; j < 16; j++){
        int colb = j*8 + 2*q;
        float2 v0; v0.x = acc[j][0]; v0.y = acc[j][1];
        float2 v1; v1.x = acc[j][2]; v1.y = acc[j][3];
        *(float2*)(Zs + (rb+gr)*132 + colb)   = v0;
        *(float2*)(Zs + (rb+gr+8)*132 + colb) = v1;
    }
    __syncthreads();

    int c = t & 63, ag = t >> 6;        // 3 atom groups
    float sf = 0, qf = 0, sc = 0, qc = 0;
    for (int a = ag; a < 8; a += 3){
        float s0 = Ssm[a*128 + c], s1 = Ssm[a*128 + 64 + c];
        #pragma unroll
        for (int m = 0; m < 12; m++){
            int r = a*12 + m;
            int gi = rIdx[r];
            float zf = Zs[r*132 + c]      + s0 + g_T[(size_t)gi*128 + c];
            float zc = Zs[r*132 + 64 + c] + s1 + g_T[(size_t)gi*128 + 64 + c];
            sf += zf; qf = fmaf(zf, zf, qf);
            sc += zc; qc = fmaf(zc, zc, qc);
        }
    }
    ps[ag*128 + c] = sf;  ps[ag*128 + 64 + c] = sc;
    pq[ag*128 + c] = qf;  pq[ag*128 + 64 + c] = qc;
    __syncthreads();
    if (t < 128){
        g_psum[blk*128 + t] = ps[t] + ps[128 + t] + ps[256 + t];
        g_psq [blk*128 + t] = pq[t] + pq[128 + t] + pq[256 + t];
    }
}

// ======================= msg pass B: BN2 + gate + sum ========================
__global__ void __launch_bounds__(192) k_msgB(const float* __restrict__ Wl,
                                              const float* __restrict__ nbr){
    extern __shared__ float sm[];
    float* NFs = sm;
    float* WTs = sm + 6528;
    float* Zs  = sm;
    float* Ssm = sm + 15232;
    int*   rIdx= (int*)(sm + 16256);
    float* pbs = sm + 16352;   // 3*64
    float* pbq = sm + 16544;   // 3*64

    int t = threadIdx.x;
    int lane = t & 31, warp = t >> 5;
    int gr = lane >> 2, q = lane & 3;
    int blk = blockIdx.x;
    int r0 = blk * MT;

    const float* nsrc = nbr + (size_t)r0 * 64;
    for (int i = t; i < MT*64; i += 192){
        NFs[(i >> 6)*68 + (i & 63)] = __uint_as_float(tf32r(nsrc[i]));
    }
    const float* wsrc = Wl + 128*128;
    for (int i = t; i < 64*128; i += 192){
        int k = i >> 7, n = i & 127;
        WTs[n*68 + k] = __uint_as_float(tf32r(wsrc[i]));
    }
    for (int i = t; i < 1024; i += 192) Ssm[i] = g_S[(size_t)blk*8*128 + i];
    for (int i = t; i < MT;   i += 192) rIdx[i] = g_idx[r0 + i];
    __syncthreads();

    float acc[16][4];
    #pragma unroll
    for (int j = 0; j < 16; j++){ acc[j][0]=0; acc[j][1]=0; acc[j][2]=0; acc[j][3]=0; }
    int rb = warp * 16;
    for (int ks = 0; ks < 8; ks++){
        int k0 = ks*8 + q;
        unsigned a0 = __float_as_uint(NFs[(rb+gr)*68 + k0]);
        unsigned a1 = __float_as_uint(NFs[(rb+gr+8)*68 + k0]);
        unsigned a2 = __float_as_uint(NFs[(rb+gr)*68 + k0 + 4]);
        unsigned a3 = __float_as_uint(NFs[(rb+gr+8)*68 + k0 + 4]);
        #pragma unroll
        for (int j = 0; j < 16; j++){
            unsigned b0 = __float_as_uint(WTs[(j*8+gr)*68 + k0]);
            unsigned b1 = __float_as_uint(WTs[(j*8+gr)*68 + k0 + 4]);
            mma8(acc[j][0], acc[j][1], acc[j][2], acc[j][3], a0, a1, a2, a3, b0, b1);
        }
    }
    __syncthreads();
    #pragma unroll
    for (int j = 0; j < 16; j++){
        int colb = j*8 + 2*q;
        float2 v0; v0.x = acc[j][0]; v0.y = acc[j][1];
        float2 v1; v1.x = acc[j][2]; v1.y = acc[j][3];
        *(float2*)(Zs + (rb+gr)*132 + colb)   = v0;
        *(float2*)(Zs + (rb+gr+8)*132 + colb) = v1;
    }
    __syncthreads();

    int c = t & 63, ag = t >> 6;
    float A2f = g_A2[c],      B2f = g_B2[c];
    float A2c = g_A2[64 + c], B2c = g_B2[64 + c];
    float bs = 0, bq = 0;
    for (int a = ag; a < 8; a += 3){
        float s0 = Ssm[a*128 + c], s1 = Ssm[a*128 + 64 + c];
        float sgate = 0;
        #pragma unroll
        for (int m = 0; m < 12; m++){
            int r = a*12 + m;
            int gi = rIdx[r];
            float zf = Zs[r*132 + c]      + s0 + g_T[(size_t)gi*128 + c];
            float zc = Zs[r*132 + 64 + c] + s1 + g_T[(size_t)gi*128 + 64 + c];
            float f  = fmaf(zf, A2f, B2f);
            float co = fmaf(zc, A2c, B2c);
            sgate += fsig_(f) * fsoftplus_(co);
        }
        g_summed[(blk*8 + a)*64 + c] = sgate;
        bs += sgate; bq = fmaf(sgate, sgate, bq);
    }
    pbs[ag*64 + c] = bs;
    pbq[ag*64 + c] = bq;
    __syncthreads();
    if (t < 64){
        g_p1s[blk*64 + t] = pbs[t] + pbs[64 + t] + pbs[128 + t];
        g_p1q[blk*64 + t] = pbq[t] + pbq[64 + t] + pbq[128 + t];
    }
}

// ---------------- BN2 stat reduction ----------------------------------------
__global__ void k_red2a(){
    int b = blockIdx.x, t = threadIdx.x;
    float s = 0, q = 0;
    for (int i = 0; i < 50; i++){
        int row = b*50 + i;
        s += g_psum[row*128 + t];
        q += g_psq [row*128 + t];
    }
    g_r2s[b*128 + t] = s; g_r2q[b*128 + t] = q;
}
__global__ void k_red2b(const float* __restrict__ g2, const float* __restrict__ b2){
    int t = threadIdx.x;
    float s = 0, q = 0;
    for (int i = 0; i < 125; i++){ s += g_r2s[i*128 + t]; q += g_r2q[i*128 + t]; }
    float inv  = 1.0f / 600000.0f;
    float mean = s * inv;
    float var  = fmaxf(q * inv - mean*mean, 0.0f);
    float rstd = rsqrtf(var + EPS);
    float A = g2[t] * rstd;
    g_A2[t] = A;
    g_B2[t] = b2[t] - mean * A;
}

// ---------------- BN1 stat reduction ----------------------------------------
__global__ void k_red1a(){
    int b = blockIdx.x, t = threadIdx.x;
    float s = 0, q = 0;
    for (int i = 0; i < 50; i++){
        int row = b*50 + i;
        s += g_p1s[row*64 + t];
        q += g_p1q[row*64 + t];
    }
    g_r1s[b*64 + t] = s; g_r1q[b*64 + t] = q;
}
__global__ void k_red1b(const float* __restrict__ g1, const float* __restrict__ b1){
    int t = threadIdx.x;
    float s = 0, q = 0;
    for (int i = 0; i < 125; i++){ s += g_r1s[i*64 + t]; q += g_r1q[i*64 + t]; }
    float inv  = 1.0f / (float)NA;
    float mean = s * inv;
    float var  = fmaxf(q * inv - mean*mean, 0.0f);
    float rstd = rsqrtf(var + EPS);
    float A = g1[t] * rstd;
    g_A1[t] = A;
    g_B1[t] = b1[t] - mean * A;
}

// ---------------- atom = softplus(atom + BN1(summed)) -----------------------
__global__ void k_update(){
    int i = blockIdx.x*256 + threadIdx.x;
    int c = i & 63;
    float v = g_atom[i] + fmaf(g_summed[i], g_A1[c], g_B1[c]);
    g_atom[i] = fsoftplus_(v);
}

// ---------------- pooling + head --------------------------------------------
__global__ void k_head(const float* __restrict__ fc1W, const float* __restrict__ fc1b,
                       const float* __restrict__ outW, const float* __restrict__ outb,
                       float* __restrict__ out){
    __shared__ float crys[128];
    __shared__ float red[128];
    int cid = blockIdx.x, t = threadIdx.x;
    if (t < 64){
        float v[10]; float s = 0;
        #pragma unroll
        for (int j = 0; j < 10; j++){ v[j] = g_atom[(cid*10 + j)*64 + t]; s += v[j]; }
        float mean = s * 0.1f;
        float q = 0;
        #pragma unroll
        for (int j = 0; j < 10; j++){ float d = v[j] - mean; q = fmaf(d, d, q); }
        float sd = sqrtf(q * (1.0f/9.0f));
        crys[t]      = fsoftplus_(mean);
        crys[64 + t] = fsoftplus_(sd);
    }
    __syncthreads();
    float acc = fc1b[t];
    #pragma unroll 4
    for (int k = 0; k < 128; k++)
        acc = fmaf(crys[k], fc1W[k*128 + t], acc);
    float hv = fsoftplus_(acc);
    red[t] = hv * outW[t];
    __syncthreads();
    for (int off = 64; off; off >>= 1){
        if (t < off) red[t] += red[t + off];
        __syncthreads();
    }
    if (t == 0) out[cid] = red[0] + outb[0];
}

// ---------------- host ------------------------------------------------------
extern "C" void kernel_launch(void* const* d_in, const int* in_sizes, int n_in,
                              void* d_out, int out_size){
    const float* orig  = (const float*)d_in[0];
    const float* nbr   = (const float*)d_in[1];
    const int*   idxr  = (const int*)  d_in[2];
    const float* embW  = (const float*)d_in[4];
    const float* embB  = (const float*)d_in[5];
    const float* msgW  = (const float*)d_in[6];
    const float* msgB  = (const float*)d_in[7];
    const float* bn2g  = (const float*)d_in[8];
    const float* bn2b  = (const float*)d_in[9];
    const float* bn1g  = (const float*)d_in[10];
    const float* bn1b  = (const float*)d_in[11];
    const float* fc1W  = (const float*)d_in[12];
    const float* fc1b  = (const float*)d_in[13];
    const float* outW  = (const float*)d_in[14];
    const float* outb  = (const float*)d_in[15];
    float* out = (float*)d_out;

    const int SMEM_EMB  = (26112 + 13056 + 64) * 4;     // 156,928
    const int SMEM_ST   = (8704 + 8704 + 128) * 4;      // 70,144
    const int SMEM_MSGA = 17120 * 4;                    // 68,480
    const int SMEM_MSGB = 16736 * 4;                    // 66,944
    cudaFuncSetAttribute(k_embed2, cudaFuncAttributeMaxDynamicSharedMemorySize, SMEM_EMB);
    cudaFuncSetAttribute(k_st2,    cudaFuncAttributeMaxDynamicSharedMemorySize, SMEM_ST);
    cudaFuncSetAttribute(k_msgA,   cudaFuncAttributeMaxDynamicSharedMemorySize, SMEM_MSGA);
    cudaFuncSetAttribute(k_msgB,   cudaFuncAttributeMaxDynamicSharedMemorySize, SMEM_MSGB);

    k_detect<<<1, 256>>>(idxr);
    k_conv<<<(NR + 255)/256, 256>>>(idxr);
    k_embed2<<<(NA + 127)/128, 256, SMEM_EMB>>>(orig, embW, embB);

    for (int i = 0; i < 3; i++){
        const float* Wl = msgW + (size_t)i*192*128;
        const float* bl = msgB + i*128;
        k_st2  <<<dim3((NA + 127)/128, 2), 256, SMEM_ST>>>(Wl, bl);
        k_msgA <<<NBLK, 192, SMEM_MSGA>>>(Wl, nbr);
        k_red2a<<<125, 128>>>();
        k_red2b<<<1, 128>>>(bn2g + i*128, bn2b + i*128);
        k_msgB <<<NBLK, 192, SMEM_MSGB>>>(Wl, nbr);
        k_red1a<<<125, 64>>>();
        k_red1b<<<1, 64>>>(bn1g + i*64, bn1b + i*64);
        k_update<<<NA*AFL/256, 256>>>();
    }
    k_head<<<NCRY, 128>>>(fc1W, fc1b, outW, outb, out);
}

// round 8
// speedup vs baseline: 1.3976x; 1.3976x over previous
#include <cuda_runtime.h>
#include <cuda_fp16.h>

#define NA 50000
#define MN 12
#define NR (NA*MN)          // 600000
#define NCRY 5000
#define ORIGF 200
#define AFL 64
#define EPS 1e-5f
#define MT 96               // msg row tile = 8 atoms
#define NBLK (NR/MT)        // 6250
#define GATOMS 16
#define GBLK (NA/GATOMS)    // 3125

// ---------------- scratch ----------------------------------------------------
__device__ float g_atom[NA*AFL];
__device__ float g_atom_t[NA*AFL];            // tf32-rounded copy
__device__ float g_S[NA*128];
__device__ float g_T[NA*128];
__device__ unsigned int g_Z2[(size_t)NR*64];  // half2(zf, zc) per (row, col)
__device__ float g_WT3[3*128*68];             // per-layer W, tf32, [half][n][k] padded 68
__device__ float g_WembT[64*204];             // emb W, tf32, [n][k] padded 204
__device__ float g_psum[NBLK*128];
__device__ float g_psq [NBLK*128];
__device__ float g_r2s[125*128];
__device__ float g_r2q[125*128];
__device__ float g_A2[128];
__device__ float g_B2[128];
__device__ float g_summed[NA*AFL];
__device__ float g_p1s[GBLK*64];
__device__ float g_p1q[GBLK*64];
__device__ float g_r1s[125*64];
__device__ float g_r1q[125*64];
__device__ float g_A1[64];
__device__ float g_B1[64];
__device__ int   g_idx[NR];
__device__ int   g_flag;

// ---------------- MUFU transcendentals --------------------------------------
__device__ __forceinline__ float mufu_ex2(float x){ float y; asm("ex2.approx.f32 %0,%1;" : "=f"(y) : "f"(x)); return y; }
__device__ __forceinline__ float mufu_lg2(float x){ float y; asm("lg2.approx.f32 %0,%1;" : "=f"(y) : "f"(x)); return y; }
__device__ __forceinline__ float mufu_rcp(float x){ float y; asm("rcp.approx.f32 %0,%1;" : "=f"(y) : "f"(x)); return y; }
__device__ __forceinline__ float fsig_(float x){
    return mufu_rcp(1.0f + mufu_ex2(-1.4426950408889634f * x));
}
__device__ __forceinline__ float fsoftplus_(float x){
    float u = mufu_ex2(-1.4426950408889634f * fabsf(x));
    return fmaxf(x, 0.0f) + 0.69314718055994531f * mufu_lg2(1.0f + u);
}

// ---------------- tf32 mma helpers ------------------------------------------
__device__ __forceinline__ unsigned tf32r(float x){
    unsigned u; asm("cvt.rna.tf32.f32 %0, %1;" : "=r"(u) : "f"(x)); return u;
}
__device__ __forceinline__ void mma8(float& c0, float& c1, float& c2, float& c3,
                                     unsigned a0, unsigned a1, unsigned a2, unsigned a3,
                                     unsigned b0, unsigned b1){
    asm volatile("mma.sync.aligned.m16n8k8.row.col.f32.tf32.tf32.f32 "
        "{%0,%1,%2,%3}, {%4,%5,%6,%7}, {%8,%9}, {%0,%1,%2,%3};"
        : "+f"(c0), "+f"(c1), "+f"(c2), "+f"(c3)
        : "r"(a0), "r"(a1), "r"(a2), "r"(a3), "r"(b0), "r"(b1));
}

// ---------------- index dtype detect + convert ------------------------------
__global__ void k_detect(const int* __restrict__ raw){
    __shared__ int s[256];
    int nz = 0;
    for (int i = threadIdx.x; i < 2048; i += 256) nz |= (raw[2*i+1] != 0);
    s[threadIdx.x] = nz;
    __syncthreads();
    for (int off = 128; off; off >>= 1){
        if (threadIdx.x < off) s[threadIdx.x] |= s[threadIdx.x + off];
        __syncthreads();
    }
    if (threadIdx.x == 0) g_flag = (s[0] == 0) ? 1 : 0;
}
__global__ void k_conv(const int* __restrict__ raw){
    int i = blockIdx.x * 256 + threadIdx.x;
    if (i < NR){
        int f = g_flag;
        g_idx[i] = raw[f ? (2*i) : i];
    }
}

// ---------------- weight prep (tf32, transposed, padded) --------------------
__global__ void k_prepw(const float* __restrict__ Wl){
    int i = blockIdx.x*256 + threadIdx.x;
    if (i < 3*128*68){
        int h = i / 8704; int rem = i - h*8704;
        int n = rem / 68; int k = rem - n*68;
        g_WT3[i] = (k < 64) ? __uint_as_float(tf32r(Wl[(h*64 + k)*128 + n])) : 0.0f;
    }
}
__global__ void k_prepemb(const float* __restrict__ W){
    int i = blockIdx.x*256 + threadIdx.x;
    if (i < 64*204){
        int n = i / 204; int k = i - n*204;
        g_WembT[i] = (k < ORIGF) ? __uint_as_float(tf32r(W[k*64 + n])) : 0.0f;
    }
}
__global__ void k_atomcvt(){
    int i = (blockIdx.x*256 + threadIdx.x)*4;        // grid exact: NA*64/4/256
    float4 v = *(const float4*)(g_atom + i);
    v.x = __uint_as_float(tf32r(v.x)); v.y = __uint_as_float(tf32r(v.y));
    v.z = __uint_as_float(tf32r(v.z)); v.w = __uint_as_float(tf32r(v.w));
    *(float4*)(g_atom_t + i) = v;
}

// ---------------- embedding via tf32 mma ------------------------------------
__global__ void __launch_bounds__(256) k_embed2(const float* __restrict__ orig,
                                                const float* __restrict__ B){
    extern __shared__ float sm[];
    float* As  = sm;            // 128 x 204
    float* WTs = sm + 26112;    // 64 x 204
    float* Bs  = sm + 39168;    // 64
    int t = threadIdx.x;
    int lane = t & 31, warp = t >> 5;
    int gr = lane >> 2, q = lane & 3;
    int r0 = blockIdx.x * 128;

    for (int i = t; i < 128*ORIGF/4; i += 256){
        int r = i / 50, kk = (i - r*50)*4;
        int row = r0 + r;
        float4 v;
        if (row < NA){
            v = *(const float4*)(orig + (size_t)row*ORIGF + kk);
            v.x = __uint_as_float(tf32r(v.x)); v.y = __uint_as_float(tf32r(v.y));
            v.z = __uint_as_float(tf32r(v.z)); v.w = __uint_as_float(tf32r(v.w));
        } else { v.x = v.y = v.z = v.w = 0.0f; }
        *(float4*)(As + r*204 + kk) = v;
    }
    for (int i = t; i < 64*204/4; i += 256)
        *(float4*)(WTs + i*4) = *(const float4*)(g_WembT + i*4);
    if (t < 64) Bs[t] = B[t];
    __syncthreads();

    float acc[8][4];
    #pragma unroll
    for (int j = 0; j < 8; j++){ acc[j][0]=0; acc[j][1]=0; acc[j][2]=0; acc[j][3]=0; }
    int rb = warp * 16;
    for (int ks = 0; ks < 25; ks++){
        int k0 = ks*8 + q;
        unsigned a0 = __float_as_uint(As[(rb+gr)*204 + k0]);
        unsigned a1 = __float_as_uint(As[(rb+gr+8)*204 + k0]);
        unsigned a2 = __float_as_uint(As[(rb+gr)*204 + k0 + 4]);
        unsigned a3 = __float_as_uint(As[(rb+gr+8)*204 + k0 + 4]);
        #pragma unroll
        for (int j = 0; j < 8; j++){
            unsigned b0 = __float_as_uint(WTs[(j*8+gr)*204 + k0]);
            unsigned b1 = __float_as_uint(WTs[(j*8+gr)*204 + k0 + 4]);
            mma8(acc[j][0], acc[j][1], acc[j][2], acc[j][3], a0, a1, a2, a3, b0, b1);
        }
    }
    #pragma unroll
    for (int j = 0; j < 8; j++){
        int colb = j*8 + 2*q;
        float b0v = Bs[colb], b1v = Bs[colb+1];
        int row = r0 + rb + gr;
        if (row < NA){
            float2 v; v.x = acc[j][0] + b0v; v.y = acc[j][1] + b1v;
            *(float2*)(g_atom + row*64 + colb) = v;
        }
        row += 8;
        if (row < NA){
            float2 v; v.x = acc[j][2] + b0v; v.y = acc[j][3] + b1v;
            *(float2*)(g_atom + row*64 + colb) = v;
        }
    }
}

// ---------------- S/T via tf32 mma: grid (391, 2) ---------------------------
__global__ void __launch_bounds__(256) k_st2(const float* __restrict__ bl){
    extern __shared__ float sm[];
    float* As  = sm;            // 128 x 68
    float* WTs = sm + 8704;     // 128 x 68
    float* Bs  = sm + 17408;    // 128
    int t = threadIdx.x;
    int lane = t & 31, warp = t >> 5;
    int gr = lane >> 2, q = lane & 3;
    int r0 = blockIdx.x * 128;
    int half = blockIdx.y;      // 0 -> S (+bias), 1 -> T

    for (int i = t; i < 2048; i += 256){      // 128*64/4 float4s
        int r = i >> 4, kk = (i & 15)*4;
        int row = r0 + r;
        float4 v;
        if (row < NA) v = *(const float4*)(g_atom_t + (size_t)row*64 + kk);
        else { v.x = v.y = v.z = v.w = 0.0f; }
        *(float4*)(As + r*68 + kk) = v;
    }
    const float* wsrc = g_WT3 + half*8704;
    for (int i = t; i < 2176; i += 256)
        *(float4*)(WTs + i*4) = *(const float4*)(wsrc + i*4);
    if (t < 128) Bs[t] = half ? 0.0f : bl[t];
    __syncthreads();

    float acc[16][4];
    #pragma unroll
    for (int j = 0; j < 16; j++){ acc[j][0]=0; acc[j][1]=0; acc[j][2]=0; acc[j][3]=0; }
    int rb = warp * 16;
    for (int ks = 0; ks < 8; ks++){
        int k0 = ks*8 + q;
        unsigned a0 = __float_as_uint(As[(rb+gr)*68 + k0]);
        unsigned a1 = __float_as_uint(As[(rb+gr+8)*68 + k0]);
        unsigned a2 = __float_as_uint(As[(rb+gr)*68 + k0 + 4]);
        unsigned a3 = __float_as_uint(As[(rb+gr+8)*68 + k0 + 4]);
        #pragma unroll
        for (int j = 0; j < 16; j++){
            unsigned b0 = __float_as_uint(WTs[(j*8+gr)*68 + k0]);
            unsigned b1 = __float_as_uint(WTs[(j*8+gr)*68 + k0 + 4]);
            mma8(acc[j][0], acc[j][1], acc[j][2], acc[j][3], a0, a1, a2, a3, b0, b1);
        }
    }
    float* dst = half ? g_T : g_S;
    #pragma unroll
    for (int j = 0; j < 16; j++){
        int colb = j*8 + 2*q;
        float b0v = Bs[colb], b1v = Bs[colb+1];
        int row = r0 + rb + gr;
        if (row < NA){
            float2 v; v.x = acc[j][0] + b0v; v.y = acc[j][1] + b1v;
            *(float2*)(dst + row*128 + colb) = v;
        }
        row += 8;
        if (row < NA){
            float2 v; v.x = acc[j][2] + b0v; v.y = acc[j][3] + b1v;
            *(float2*)(dst + row*128 + colb) = v;
        }
    }
}

// ------- msg: Z = nf@Wnf + S + T (tf32 mma), stats + half2 Z2 store ---------
// smem floats: NFs[0,6528) WTs[6528,15232) | Zs alias [0,12672)
//              Ssm[15232,16256) rIdx@16256 (96 ints) ps[16352,16736) pq[16736,17120)
__global__ void __launch_bounds__(192) k_msg(const float* __restrict__ nbr){
    extern __shared__ float sm[];
    float* NFs = sm;
    float* WTs = sm + 6528;
    float* Zs  = sm;
    float* Ssm = sm + 15232;
    int*   rIdx= (int*)(sm + 16256);
    float* ps  = sm + 16352;
    float* pq  = sm + 16736;

    int t = threadIdx.x;
    int lane = t & 31, warp = t >> 5;
    int gr = lane >> 2, q = lane & 3;
    int blk = blockIdx.x;
    int r0 = blk * MT;

    const float* nsrc = nbr + (size_t)r0 * 64;
    for (int i = t; i < MT*64/4; i += 192){
        int r = i >> 4, kk = (i & 15)*4;
        float4 v = *(const float4*)(nsrc + r*64 + kk);
        v.x = __uint_as_float(tf32r(v.x)); v.y = __uint_as_float(tf32r(v.y));
        v.z = __uint_as_float(tf32r(v.z)); v.w = __uint_as_float(tf32r(v.w));
        *(float4*)(NFs + r*68 + kk) = v;
    }
    const float* wsrc = g_WT3 + 2*8704;
    for (int i = t; i < 2176; i += 192)
        *(float4*)(WTs + i*4) = *(const float4*)(wsrc + i*4);
    for (int i = t; i < 256; i += 192)
        *(float4*)(Ssm + i*4) = *(const float4*)(g_S + (size_t)blk*8*128 + i*4);
    if (t < MT) rIdx[t] = g_idx[r0 + t];
    __syncthreads();

    float acc[16][4];
    #pragma unroll
    for (int j = 0; j < 16; j++){ acc[j][0]=0; acc[j][1]=0; acc[j][2]=0; acc[j][3]=0; }
    int rb = warp * 16;
    for (int ks = 0; ks < 8; ks++){
        int k0 = ks*8 + q;
        unsigned a0 = __float_as_uint(NFs[(rb+gr)*68 + k0]);
        unsigned a1 = __float_as_uint(NFs[(rb+gr+8)*68 + k0]);
        unsigned a2 = __float_as_uint(NFs[(rb+gr)*68 + k0 + 4]);
        unsigned a3 = __float_as_uint(NFs[(rb+gr+8)*68 + k0 + 4]);
        #pragma unroll
        for (int j = 0; j < 16; j++){
            unsigned b0 = __float_as_uint(WTs[(j*8+gr)*68 + k0]);
            unsigned b1 = __float_as_uint(WTs[(j*8+gr)*68 + k0 + 4]);
            mma8(acc[j][0], acc[j][1], acc[j][2], acc[j][3], a0, a1, a2, a3, b0, b1);
        }
    }
    __syncthreads();   // NFs/WTs dead; Zs takes over
    #pragma unroll
    for (int j = 0; j < 16; j++){
        int colb = j*8 + 2*q;
        float2 v0; v0.x = acc[j][0]; v0.y = acc[j][1];
        float2 v1; v1.x = acc[j][2]; v1.y = acc[j][3];
        *(float2*)(Zs + (rb+gr)*132 + colb)   = v0;
        *(float2*)(Zs + (rb+gr+8)*132 + colb) = v1;
    }
    __syncthreads();

    int c = t & 63, ag = t >> 6;        // 3 groups x 32 rows
    float sf = 0, qf = 0, sc = 0, qc = 0;
    #pragma unroll 4
    for (int rr = 0; rr < 32; rr++){
        int r = ag*32 + rr;
        int gi = rIdx[r];
        int a  = r / 12;
        float zf = Zs[r*132 + c]      + Ssm[a*128 + c]      + g_T[(size_t)gi*128 + c];
        float zc = Zs[r*132 + 64 + c] + Ssm[a*128 + 64 + c] + g_T[(size_t)gi*128 + 64 + c];
        __half2 h = __floats2half2_rn(zf, zc);
        g_Z2[(size_t)(r0 + r)*64 + c] = *(unsigned*)&h;
        sf += zf; qf = fmaf(zf, zf, qf);
        sc += zc; qc = fmaf(zc, zc, qc);
    }
    ps[ag*128 + c] = sf;  ps[ag*128 + 64 + c] = sc;
    pq[ag*128 + c] = qf;  pq[ag*128 + 64 + c] = qc;
    __syncthreads();
    if (t < 128){
        g_psum[blk*128 + t] = ps[t] + ps[128 + t] + ps[256 + t];
        g_psq [blk*128 + t] = pq[t] + pq[128 + t] + pq[256 + t];
    }
}

// ---------------- BN2 stat reduction ----------------------------------------
__global__ void k_red2a(){
    int b = blockIdx.x, t = threadIdx.x;
    float s = 0, q = 0;
    for (int i = 0; i < 50; i++){
        int row = b*50 + i;
        s += g_psum[row*128 + t];
        q += g_psq [row*128 + t];
    }
    g_r2s[b*128 + t] = s; g_r2q[b*128 + t] = q;
}
__global__ void k_red2b(const float* __restrict__ g2, const float* __restrict__ b2){
    int t = threadIdx.x;
    float s = 0, q = 0;
    for (int i = 0; i < 125; i++){ s += g_r2s[i*128 + t]; q += g_r2q[i*128 + t]; }
    float inv  = 1.0f / 600000.0f;
    float mean = s * inv;
    float var  = fmaxf(q * inv - mean*mean, 0.0f);
    float rstd = rsqrtf(var + EPS);
    float A = g2[t] * rstd;
    g_A2[t] = A;
    g_B2[t] = b2[t] - mean * A;
}

// ---------------- gate: uint2 Z2 read, BN2 + sig*softplus + sum -------------
__global__ void __launch_bounds__(256) k_gate3(){
    __shared__ float pbs[8][64];
    __shared__ float pbq[8][64];
    int t = threadIdx.x;
    int c2 = t & 31, ag = t >> 5;     // 8 groups x 2 atoms
    int c0 = 2*c2;
    int blk = blockIdx.x;
    float A2f0 = g_A2[c0],      A2f1 = g_A2[c0+1];
    float B2f0 = g_B2[c0],      B2f1 = g_B2[c0+1];
    float A2c0 = g_A2[64 + c0], A2c1 = g_A2[64 + c0+1];
    float B2c0 = g_B2[64 + c0], B2c1 = g_B2[64 + c0+1];
    float bs0 = 0, bq0 = 0, bs1 = 0, bq1 = 0;
    #pragma unroll 1
    for (int a = 0; a < 2; a++){
        int atom = blk*GATOMS + ag*2 + a;
        const uint2* zr = (const uint2*)(g_Z2 + (size_t)atom*12*64) + c2;
        float s0 = 0, s1 = 0;
        #pragma unroll
        for (int m = 0; m < 12; m++){
            uint2 zz = zr[m*32];
            __half2 h0 = *(__half2*)&zz.x;
            __half2 h1 = *(__half2*)&zz.y;
            float zf0 = __low2float(h0), zc0 = __high2float(h0);
            float zf1 = __low2float(h1), zc1 = __high2float(h1);
            s0 += fsig_(fmaf(zf0, A2f0, B2f0)) * fsoftplus_(fmaf(zc0, A2c0, B2c0));
            s1 += fsig_(fmaf(zf1, A2f1, B2f1)) * fsoftplus_(fmaf(zc1, A2c1, B2c1));
        }
        float2 st; st.x = s0; st.y = s1;
        *(float2*)(g_summed + atom*64 + c0) = st;
        bs0 += s0; bq0 = fmaf(s0, s0, bq0);
        bs1 += s1; bq1 = fmaf(s1, s1, bq1);
    }
    pbs[ag][c0] = bs0; pbs[ag][c0+1] = bs1;
    pbq[ag][c0] = bq0; pbq[ag][c0+1] = bq1;
    __syncthreads();
    if (t < 64){
        float s = 0, q = 0;
        #pragma unroll
        for (int g = 0; g < 8; g++){ s += pbs[g][t]; q += pbq[g][t]; }
        g_p1s[blk*64 + t] = s;
        g_p1q[blk*64 + t] = q;
    }
}

// ---------------- BN1 stat reduction ----------------------------------------
__global__ void k_red1a(){
    int b = blockIdx.x, t = threadIdx.x;
    float s = 0, q = 0;
    for (int i = 0; i < 25; i++){
        int row = b*25 + i;
        s += g_p1s[row*64 + t];
        q += g_p1q[row*64 + t];
    }
    g_r1s[b*64 + t] = s; g_r1q[b*64 + t] = q;
}
__global__ void k_red1b(const float* __restrict__ g1, const float* __restrict__ b1){
    int t = threadIdx.x;
    float s = 0, q = 0;
    for (int i = 0; i < 125; i++){ s += g_r1s[i*64 + t]; q += g_r1q[i*64 + t]; }
    float inv  = 1.0f / (float)NA;
    float mean = s * inv;
    float var  = fmaxf(q * inv - mean*mean, 0.0f);
    float rstd = rsqrtf(var + EPS);
    float A = g1[t] * rstd;
    g_A1[t] = A;
    g_B1[t] = b1[t] - mean * A;
}

// ---------------- atom = softplus(atom + BN1(summed)) -----------------------
__global__ void k_update4(){
    int i = (blockIdx.x*256 + threadIdx.x)*4;   // grid exact: NA*64/4/256
    int c = i & 63;
    float4 a = *(const float4*)(g_atom + i);
    float4 s = *(const float4*)(g_summed + i);
    float4 v;
    v.x = fsoftplus_(a.x + fmaf(s.x, g_A1[c],   g_B1[c]));
    v.y = fsoftplus_(a.y + fmaf(s.y, g_A1[c+1], g_B1[c+1]));
    v.z = fsoftplus_(a.z + fmaf(s.z, g_A1[c+2], g_B1[c+2]));
    v.w = fsoftplus_(a.w + fmaf(s.w, g_A1[c+3], g_B1[c+3]));
    *(float4*)(g_atom + i) = v;
}

// ---------------- pooling + head --------------------------------------------
__global__ void k_head(const float* __restrict__ fc1W, const float* __restrict__ fc1b,
                       const float* __restrict__ outW, const float* __restrict__ outb,
                       float* __restrict__ out){
    __shared__ float crys[128];
    __shared__ float red[128];
    int cid = blockIdx.x, t = threadIdx.x;
    if (t < 64){
        float v[10]; float s = 0;
        #pragma unroll
        for (int j = 0; j < 10; j++){ v[j] = g_atom[(cid*10 + j)*64 + t]; s += v[j]; }
        float mean = s * 0.1f;
        float q = 0;
        #pragma unroll
        for (int j = 0; j < 10; j++){ float d = v[j] - mean; q = fmaf(d, d, q); }
        float sd = sqrtf(q * (1.0f/9.0f));
        crys[t]      = fsoftplus_(mean);
        crys[64 + t] = fsoftplus_(sd);
    }
    __syncthreads();
    float acc = fc1b[t];
    #pragma unroll 4
    for (int k = 0; k < 128; k++)
        acc = fmaf(crys[k], fc1W[k*128 + t], acc);
    float hv = fsoftplus_(acc);
    red[t] = hv * outW[t];
    __syncthreads();
    for (int off = 64; off; off >>= 1){
        if (t < off) red[t] += red[t + off];
        __syncthreads();
    }
    if (t == 0) out[cid] = red[0] + outb[0];
}

// ---------------- host ------------------------------------------------------
extern "C" void kernel_launch(void* const* d_in, const int* in_sizes, int n_in,
                              void* d_out, int out_size){
    const float* orig  = (const float*)d_in[0];
    const float* nbr   = (const float*)d_in[1];
    const int*   idxr  = (const int*)  d_in[2];
    const float* embW  = (const float*)d_in[4];
    const float* embB  = (const float*)d_in[5];
    const float* msgW  = (const float*)d_in[6];
    const float* msgB  = (const float*)d_in[7];
    const float* bn2g  = (const float*)d_in[8];
    const float* bn2b  = (const float*)d_in[9];
    const float* bn1g  = (const float*)d_in[10];
    const float* bn1b  = (const float*)d_in[11];
    const float* fc1W  = (const float*)d_in[12];
    const float* fc1b  = (const float*)d_in[13];
    const float* outW  = (const float*)d_in[14];
    const float* outb  = (const float*)d_in[15];
    float* out = (float*)d_out;

    const int SMEM_EMB  = (26112 + 13056 + 64) * 4;     // 156,928
    const int SMEM_ST   = (8704 + 8704 + 128) * 4;      // 70,144
    const int SMEM_MSG  = 17120 * 4;                    // 68,480
    cudaFuncSetAttribute(k_embed2, cudaFuncAttributeMaxDynamicSharedMemorySize, SMEM_EMB);
    cudaFuncSetAttribute(k_st2,    cudaFuncAttributeMaxDynamicSharedMemorySize, SMEM_ST);
    cudaFuncSetAttribute(k_msg,    cudaFuncAttributeMaxDynamicSharedMemorySize, SMEM_MSG);

    k_detect<<<1, 256>>>(idxr);
    k_conv<<<(NR + 255)/256, 256>>>(idxr);
    k_prepemb<<<51, 256>>>(embW);
    k_embed2<<<(NA + 127)/128, 256, SMEM_EMB>>>(orig, embB);

    for (int i = 0; i < 3; i++){
        const float* Wl = msgW + (size_t)i*192*128;
        const float* bl = msgB + i*128;
        k_prepw  <<<102, 256>>>(Wl);
        k_atomcvt<<<3125, 256>>>();
        k_st2    <<<dim3((NA + 127)/128, 2), 256, SMEM_ST>>>(bl);
        k_msg    <<<NBLK, 192, SMEM_MSG>>>(nbr);
        k_red2a  <<<125, 128>>>();
        k_red2b  <<<1, 128>>>(bn2g + i*128, bn2b + i*128);
        k_gate3  <<<GBLK, 256>>>();
        k_red1a  <<<125, 64>>>();
        k_red1b  <<<1, 64>>>(bn1g + i*64, bn1b + i*64);
        k_update4<<<3125, 256>>>();
    }
    k_head<<<NCRY, 128>>>(fc1W, fc1b, outW, outb, out);
}